// round 13
// baseline (speedup 1.0000x reference)
#include <cuda_runtime.h>
#include <math.h>

#define IMG    224
#define PSIDE  112
#define P      12544
#define BATCH  32
#define NC     10
#define GB     4                   // batches per block/thread
#define TPB    128
#define NROW   112                 // one block per patch-row
#define NBG    (BATCH / GB)        // 8
#define NBLOCKS (NROW * NBG)       // 896
#define NWARP  4
#define RSTR   112                 // partial stride: 112 contiguous per (b,c)
#define XBYTES 1792                // 2 image rows = 448 floats
#define WBYTES 1792                // 112 float4 per class-slice
#define TXTOT  (GB * XBYTES + NC * WBYTES)   // 25088

typedef unsigned long long u64;

__device__ float    g_part[NC * BATCH * RSTR];
__device__ unsigned g_ctr = 0;

#define PK(d, lo, hi)    asm("mov.b64 %0, {%1, %2};" : "=l"(d) : "f"(lo), "f"(hi))
#define FMA2(d, a, b, c) asm("fma.rn.f32x2 %0, %1, %2, %3;" : "=l"(d) : "l"(a), "l"(b), "l"(c))
#define ADD2(d, a, b)    asm("add.rn.f32x2 %0, %1, %2;" : "=l"(d) : "l"(a), "l"(b))

__device__ __forceinline__ float ldcg(const float* p) {
    float v; asm volatile("ld.global.cg.f32 %0, [%1];" : "=f"(v) : "l"(p)); return v;
}
__device__ __forceinline__ float4 ldcg4(const float* p) {
    float4 v;
    asm volatile("ld.global.cg.v4.f32 {%0,%1,%2,%3}, [%4];"
                 : "=f"(v.x), "=f"(v.y), "=f"(v.z), "=f"(v.w) : "l"(p));
    return v;
}
__device__ __forceinline__ unsigned smem_u32(const void* p) {
    return (unsigned)__cvta_generic_to_shared(p);
}

// Block 1 (MUFU, phases folded): a[5] = {p0, cos p1, p3, cos p4, sin p2*sin p4}
//   Z0 = cos(d0+p0);  Z1 = Z0*cos(p1)*cos(d1)
//   Z2 = cos(p4)cos(d2) + sin(p2)sin(p4)*sin(d2)*sin(d3+p3);  Z3 = cos(d2)cos(d3+p3)
__device__ __forceinline__ void qblock1(const float a[5],
                                        float d0, float d1, float d2, float d3,
                                        float& z0, float& z1, float& z2, float& z3) {
    float cA = __cosf(d0 + a[0]);
    z0 = cA;
    z1 = cA * a[1] * __cosf(d1);
    float s2, c2; __sincosf(d2, &s2, &c2);
    float sB, cB; __sincosf(d3 + a[2], &sB, &cB);
    z2 = a[3] * c2 + a[4] * s2 * sB;
    z3 = c2 * cB;
}

// Block 2 (MUFU, angle-addition on params):
// c[7] = {cos q0, sin q0, cos q1, cos q3, sin q3, cos q4, sin q2*sin q4}
__device__ __forceinline__ void qblock2(const float c[7],
                                        float d0, float d1, float d2, float d3,
                                        float& z0, float& z1, float& z2, float& z3) {
    float s0, c0; __sincosf(d0, &s0, &c0);
    float cA = c0 * c[0] - s0 * c[1];
    z0 = cA;
    z1 = cA * c[2] * __cosf(d1);
    float s2, c2; __sincosf(d2, &s2, &c2);
    float s3, c3; __sincosf(d3, &s3, &c3);
    float cB = c3 * c[3] - s3 * c[4];
    float sB = s3 * c[3] + c3 * c[4];
    z2 = c[5] * c2 + c[6] * s2 * sB;
    z3 = c2 * cB;
}

__global__ void __launch_bounds__(TPB)
k_fused(const float* __restrict__ x,
        const float* __restrict__ rl1, const float* __restrict__ rl2,
        const float* __restrict__ W,   const float* __restrict__ bias,
        float* __restrict__ out) {
    __shared__ __align__(16) float  s_x[GB][448];      // rows 2r,2r+1 per batch
    __shared__ __align__(16) float4 s_w[NC][NROW];     // W slice per class
    __shared__ __align__(8)  u64    mbar;
    __shared__ u64   sm2[NWARP][GB * NC / 2];
    __shared__ float s_lg[BATCH][NC];
    __shared__ int   lastFlag;

    const int tid = threadIdx.x;
    const int r   = blockIdx.x;              // patch row [0,112)
    const int b0  = blockIdx.y * GB;
    const unsigned mb = smem_u32(&mbar);

    // ---- 1. one-thread bulk-async fetch of the block's entire input ----
    if (tid == 0) {
        asm volatile("mbarrier.init.shared.b64 [%0], 1;" :: "r"(mb) : "memory");
    }
    __syncthreads();
    if (tid == 0) {
        asm volatile("mbarrier.arrive.expect_tx.shared.b64 _, [%0], %1;"
                     :: "r"(mb), "r"(TXTOT) : "memory");
        #pragma unroll
        for (int q = 0; q < GB; q++) {
            const float* src = x + (size_t)(b0 + q) * (IMG * IMG) + (2 * r) * IMG;
            asm volatile(
                "cp.async.bulk.shared::cluster.global.mbarrier::complete_tx::bytes "
                "[%0], [%1], %2, [%3];"
                :: "r"(smem_u32(&s_x[q][0])), "l"(src), "r"(XBYTES), "r"(mb) : "memory");
        }
        #pragma unroll
        for (int c = 0; c < NC; c++) {
            const float4* src = (const float4*)W + (size_t)c * P + r * NROW;
            asm volatile(
                "cp.async.bulk.shared::cluster.global.mbarrier::complete_tx::bytes "
                "[%0], [%1], %2, [%3];"
                :: "r"(smem_u32(&s_w[c][0])), "l"(src), "r"(WBYTES), "r"(mb) : "memory");
        }
    }

    // ---- 2. consts (MUFU) while bulk loads are in flight ----
    float a1[5];
    a1[0] = __ldg(rl1 + 0);
    a1[1] = __cosf(__ldg(rl1 + 1));
    a1[2] = __ldg(rl1 + 3);
    {
        float s4, c4; __sincosf(__ldg(rl1 + 4), &s4, &c4);
        a1[3] = c4;
        a1[4] = __sinf(__ldg(rl1 + 2)) * s4;
    }
    float c2c[7];
    {
        float s, co;
        __sincosf(__ldg(rl2 + 0), &s, &co); c2c[0] = co; c2c[1] = s;
        c2c[2] = __cosf(__ldg(rl2 + 1));
        __sincosf(__ldg(rl2 + 3), &s, &co); c2c[3] = co; c2c[4] = s;
        float s4, c4; __sincosf(__ldg(rl2 + 4), &s4, &c4);
        c2c[5] = c4;
        c2c[6] = __sinf(__ldg(rl2 + 2)) * s4;
    }

    // ---- 3. wait for data ----
    {
        unsigned done;
        asm volatile(
            "{\n\t.reg .pred p;\n\t"
            "mbarrier.try_wait.parity.acquire.cta.shared::cta.b64 p, [%1], 0;\n\t"
            "selp.b32 %0, 1, 0, p;\n\t}"
            : "=r"(done) : "r"(mb) : "memory");
        while (!done) {
            asm volatile(
                "{\n\t.reg .pred p;\n\t"
                "mbarrier.try_wait.parity.acquire.cta.shared::cta.b64 p, [%1], 0, 0x989680;\n\t"
                "selp.b32 %0, 1, 0, p;\n\t}"
                : "=r"(done) : "r"(mb) : "memory");
        }
    }

    // ---- 4. circuits: thread t = patch t of this row, GB batches ----
    const int  tw   = (tid < NROW) ? tid : 0;
    const bool live = (tid < NROW);
    const bool edge = (tw == NROW - 1);

    u64 zr[4][GB];
    #pragma unroll
    for (int q = 0; q < GB; q++) {
        const float* sx = s_x[q];
        float f0 = sx[2 * tw];
        float f1 = sx[2 * tw + 1];
        float f2 = edge ? sx[224 + 222] : sx[2 * tw + 2];
        float f3 = edge ? sx[224 + 223] : sx[224 + 2 * tw];
        float m0, m1, m2, m3, n0, n1, n2, n3;
        qblock1(a1,  f0, f1, f2, f3, m0, m1, m2, m3);
        qblock2(c2c, m0, m1, m2, m3, n0, n1, n2, n3);
        float t0 = m0 + n0, t1 = m1 + n1, t2 = m2 + n2, t3 = m3 + n3;
        if (!live) { t0 = t1 = t2 = t3 = 0.f; }
        PK(zr[0][q], t0, t0);
        PK(zr[1][q], t1, t1);
        PK(zr[2][q], t2, t2);
        PK(zr[3][q], t3, t3);
    }

    // ---- 5. GEMV from smem (LDS.128, conflict-free), packed class pairs ----
    u64 acc2[GB][NC / 2];
    #pragma unroll
    for (int cp = 0; cp < NC / 2; cp++) {
        float4 wA = s_w[2 * cp][tw];
        float4 wB = s_w[2 * cp + 1][tw];
        u64 wx, wy, wz, ww;
        PK(wx, wA.x, wB.x); PK(wy, wA.y, wB.y);
        PK(wz, wA.z, wB.z); PK(ww, wA.w, wB.w);
        #pragma unroll
        for (int q = 0; q < GB; q++) {
            u64 a = 0ull;
            FMA2(a, zr[0][q], wx, a);
            FMA2(a, zr[1][q], wy, a);
            FMA2(a, zr[2][q], wz, a);
            FMA2(a, zr[3][q], ww, a);
            acc2[q][cp] = a;
        }
    }

    // ---- 6. warp reduce packed pairs, then cross-warp via shared ----
    #pragma unroll
    for (int q = 0; q < GB; q++)
        #pragma unroll
        for (int cp = 0; cp < NC / 2; cp++) {
            u64 v = acc2[q][cp];
            #pragma unroll
            for (int off = 16; off > 0; off >>= 1) {
                u64 o = __shfl_down_sync(0xffffffffu, v, off);
                ADD2(v, v, o);
            }
            acc2[q][cp] = v;
        }

    const int warp = tid >> 5, lane = tid & 31;
    if (lane == 0) {
        #pragma unroll
        for (int q = 0; q < GB; q++)
            #pragma unroll
            for (int cp = 0; cp < NC / 2; cp++)
                sm2[warp][q * (NC / 2) + cp] = acc2[q][cp];
    }
    __syncthreads();

    if (tid < GB * NC) {
        const int q = tid / NC, c = tid - q * NC;
        float s = 0.f;
        #pragma unroll
        for (int w = 0; w < NWARP; w++)
            s += ((const float*)sm2[w])[tid];
        g_part[(c * BATCH + (b0 + q)) * RSTR + r] = s;
    }

    // ---- 7. grid-wide finalize by last block ----
    __threadfence();
    __syncthreads();
    if (tid == 0) lastFlag = (atomicAdd(&g_ctr, 1u) == NBLOCKS - 1);
    __syncthreads();
    if (!lastFlag) return;

    __threadfence();   // acquire
    #pragma unroll
    for (int u = tid; u < BATCH * NC; u += TPB) {
        const int b = u / NC, c = u - b * NC;
        const float* base = g_part + (c * BATCH + b) * RSTR;   // 112 contiguous
        float s = __ldg(bias + c);
        #pragma unroll
        for (int k = 0; k < RSTR / 4; k++) {
            float4 v = ldcg4(base + 4 * k);
            s += (v.x + v.y) + (v.z + v.w);
        }
        s_lg[b][c] = s;
    }
    __syncthreads();
    if (tid < BATCH) {
        float lg[NC];
        #pragma unroll
        for (int c = 0; c < NC; c++) lg[c] = s_lg[tid][c];
        float mx = lg[0];
        #pragma unroll
        for (int c = 1; c < NC; c++) mx = fmaxf(mx, lg[c]);
        float se = 0.f;
        #pragma unroll
        for (int c = 0; c < NC; c++) se += expf(lg[c] - mx);
        const float lse = logf(se);
        #pragma unroll
        for (int c = 0; c < NC; c++) out[tid * NC + c] = lg[c] - mx - lse;
    }
    if (tid == 0) g_ctr = 0;   // reset for next graph replay
}

extern "C" void kernel_launch(void* const* d_in, const int* in_sizes, int n_in,
                              void* d_out, int out_size) {
    const float* x    = (const float*)d_in[0];
    const float* rl1  = (const float*)d_in[1];
    const float* rl2  = (const float*)d_in[2];
    const float* W    = (const float*)d_in[3];
    const float* bias = (const float*)d_in[4];
    float* out        = (float*)d_out;

    k_fused<<<dim3(NROW, NBG), TPB>>>(x, rl1, rl2, W, bias, out);
}

// round 14
// speedup vs baseline: 1.7098x; 1.7098x over previous
#include <cuda_runtime.h>
#include <math.h>

#define IMG    224
#define PSIDE  112
#define P      12544
#define BATCH  32
#define NC     10
#define KP     2                  // patches per thread
#define GB     2                  // batches per thread
#define ROWG   (PSIDE / KP)       // 56
#define PG     (P / KP)           // 6272
#define TPB    128
#define BLKX   (PG / TPB)         // 49
#define NBG    (BATCH / GB)       // 16
#define NWARP  (TPB / 32)
#define BLKS   52                 // padded stride for g_part

typedef unsigned long long u64;

__device__ float    g_part[NC * BATCH * BLKS];
__device__ unsigned g_ctrs[NBG];   // zero-initialized; each group resets its own

#define PK(d, lo, hi)    asm("mov.b64 %0, {%1, %2};" : "=l"(d) : "f"(lo), "f"(hi))
#define FMA2(d, a, b, c) asm("fma.rn.f32x2 %0, %1, %2, %3;" : "=l"(d) : "l"(a), "l"(b), "l"(c))
#define ADD2(d, a, b)    asm("add.rn.f32x2 %0, %1, %2;" : "=l"(d) : "l"(a), "l"(b))
// Opaque zero: ptxas cannot fold or hoist loads whose address depends on it.
#define OPAQUE_ZERO(z, v) asm("and.b32 %0, %1, 0;" : "=r"(z) : "r"(__float_as_int(v)))

__device__ __forceinline__ float ldcg(const float* p) {
    float v; asm volatile("ld.global.cg.f32 %0, [%1];" : "=f"(v) : "l"(p)); return v;
}
__device__ __forceinline__ float4 ldcg4(const float* p) {
    float4 v;
    asm volatile("ld.global.cg.v4.f32 {%0,%1,%2,%3}, [%4];"
                 : "=f"(v.x), "=f"(v.y), "=f"(v.z), "=f"(v.w) : "l"(p));
    return v;
}

// Block 1 (MUFU, phases folded into args): a[5] = {p0, cos p1, p3, cos p4, sin p2*sin p4}
//   Z0 = cos(d0+p0);  Z1 = Z0*cos(p1)*cos(d1)
//   Z2 = cos(p4)cos(d2) + sin(p2)sin(p4)*sin(d2)*sin(d3+p3);  Z3 = cos(d2)cos(d3+p3)
__device__ __forceinline__ void qblock1(const float a[5],
                                        float d0, float d1, float d2, float d3,
                                        float& z0, float& z1, float& z2, float& z3) {
    float cA = __cosf(d0 + a[0]);
    z0 = cA;
    z1 = cA * a[1] * __cosf(d1);
    float s2, c2; __sincosf(d2, &s2, &c2);
    float sB, cB; __sincosf(d3 + a[2], &sB, &cB);
    z2 = a[3] * c2 + a[4] * s2 * sB;
    z3 = c2 * cB;
}

// Block 2 (MUFU, angle-addition on params):
// c[7] = {cos q0, sin q0, cos q1, cos q3, sin q3, cos q4, sin q2*sin q4}
__device__ __forceinline__ void qblock2(const float c[7],
                                        float d0, float d1, float d2, float d3,
                                        float& z0, float& z1, float& z2, float& z3) {
    float s0, c0; __sincosf(d0, &s0, &c0);
    float cA = c0 * c[0] - s0 * c[1];
    z0 = cA;
    z1 = cA * c[2] * __cosf(d1);
    float s2, c2; __sincosf(d2, &s2, &c2);
    float s3, c3; __sincosf(d3, &s3, &c3);
    float cB = c3 * c[3] - s3 * c[4];
    float sB = s3 * c[3] + c3 * c[4];
    z2 = c[5] * c2 + c[6] * s2 * sB;
    z3 = c2 * cB;
}

__global__ void __launch_bounds__(TPB)
k_fused(const float* __restrict__ x,
        const float* __restrict__ rl1, const float* __restrict__ rl2,
        const float* __restrict__ W,   const float* __restrict__ bias,
        float* __restrict__ out) {
    const int tid  = threadIdx.x;
    const int blk  = blockIdx.x;
    const int grp  = blockIdx.y;                   // batch group [0,16)
    const int pg   = blk * TPB + tid;              // patch-group [0, 6272)
    const int b0   = grp * GB;
    const int r    = pg / ROWG;
    const int g    = pg - r * ROWG;
    const bool edge = (g == ROWG - 1);
    const int pbase = r * PSIDE + g * KP;

    // ---- x loads (small front batch) ----
    const float* Xb = x + (size_t)b0 * (IMG * IMG) + (2 * r) * IMG + g * (2 * KP);
    float4 r0[GB], r1[GB]; float e4[GB];
    #pragma unroll
    for (int q = 0; q < GB; q++) {
        const float* p0 = Xb + q * (IMG * IMG);
        r0[q] = *(const float4*)p0;
        r1[q] = *(const float4*)(p0 + IMG);
        e4[q] = edge ? 0.f : __ldg(p0 + 4);
    }

    // ---- consts (MUFU; overlaps x-load latency) ----
    float a1[5];
    a1[0] = __ldg(rl1 + 0);
    a1[1] = __cosf(__ldg(rl1 + 1));
    a1[2] = __ldg(rl1 + 3);
    {
        float s4, c4; __sincosf(__ldg(rl1 + 4), &s4, &c4);
        a1[3] = c4;
        a1[4] = __sinf(__ldg(rl1 + 2)) * s4;
    }
    float c2c[7];
    {
        float s, co;
        __sincosf(__ldg(rl2 + 0), &s, &co); c2c[0] = co; c2c[1] = s;
        c2c[2] = __cosf(__ldg(rl2 + 1));
        __sincosf(__ldg(rl2 + 3), &s, &co); c2c[3] = co; c2c[4] = s;
        float s4, c4; __sincosf(__ldg(rl2 + 4), &s4, &c4);
        c2c[5] = c4;
        c2c[6] = __sinf(__ldg(rl2 + 2)) * s4;
    }

    u64 acc2[GB][NC / 2];
    #pragma unroll
    for (int q = 0; q < GB; q++)
        #pragma unroll
        for (int cp = 0; cp < NC / 2; cp++) acc2[q][cp] = 0ull;

    const float4* __restrict__ W4 = (const float4*)W;

    #pragma unroll
    for (int i = 0; i < KP; i++) {
        u64 zr[4][GB];
        float gate = 0.f;
        #pragma unroll
        for (int q = 0; q < GB; q++) {
            float f0, f1, f2, f3;
            if (i == 0) { f0 = r0[q].x; f1 = r0[q].y; f2 = r0[q].z; f3 = r1[q].x; }
            else {
                f0 = r0[q].z; f1 = r0[q].w;
                if (edge) { f2 = r1[q].z; f3 = r1[q].w; }
                else      { f2 = e4[q];   f3 = r1[q].z; }
            }
            float m0, m1, m2, m3, n0, n1, n2, n3;
            qblock1(a1,  f0, f1, f2, f3, m0, m1, m2, m3);
            qblock2(c2c, m0, m1, m2, m3, n0, n1, n2, n3);
            float t0 = m0 + n0, t1 = m1 + n1, t2 = m2 + n2, t3 = m3 + n3;
            PK(zr[0][q], t0, t0);
            PK(zr[1][q], t1, t1);
            PK(zr[2][q], t2, t2);
            PK(zr[3][q], t3, t3);
            gate = t0;
        }

        // W loads gated behind the circuit (mid-kernel burst, cannot be hoisted)
        int zoff;
        OPAQUE_ZERO(zoff, gate);
        const float4* wp = W4 + pbase + i + zoff;
        #pragma unroll
        for (int cp = 0; cp < NC / 2; cp++) {
            float4 wA = __ldg(wp + (size_t)(2 * cp)     * P);
            float4 wB = __ldg(wp + (size_t)(2 * cp + 1) * P);
            u64 wx, wy, wz, ww;
            PK(wx, wA.x, wB.x); PK(wy, wA.y, wB.y);
            PK(wz, wA.z, wB.z); PK(ww, wA.w, wB.w);
            #pragma unroll
            for (int q = 0; q < GB; q++) {
                FMA2(acc2[q][cp], zr[0][q], wx, acc2[q][cp]);
                FMA2(acc2[q][cp], zr[1][q], wy, acc2[q][cp]);
                FMA2(acc2[q][cp], zr[2][q], wz, acc2[q][cp]);
                FMA2(acc2[q][cp], zr[3][q], ww, acc2[q][cp]);
            }
        }
    }

    // ---- warp reduce packed pairs, then cross-warp via shared ----
    #pragma unroll
    for (int q = 0; q < GB; q++)
        #pragma unroll
        for (int cp = 0; cp < NC / 2; cp++) {
            u64 v = acc2[q][cp];
            #pragma unroll
            for (int off = 16; off > 0; off >>= 1) {
                u64 o = __shfl_down_sync(0xffffffffu, v, off);
                ADD2(v, v, o);
            }
            acc2[q][cp] = v;
        }

    __shared__ u64 sm2[NWARP][GB * NC / 2];
    const int warp = tid >> 5, lane = tid & 31;
    if (lane == 0) {
        #pragma unroll
        for (int q = 0; q < GB; q++)
            #pragma unroll
            for (int cp = 0; cp < NC / 2; cp++)
                sm2[warp][q * (NC / 2) + cp] = acc2[q][cp];
    }
    __syncthreads();

    if (tid < GB * NC) {
        const int q = tid / NC, c = tid - q * NC;
        float s = 0.f;
        #pragma unroll
        for (int w = 0; w < NWARP; w++)
            s += ((const float*)sm2[w])[tid];
        g_part[(c * BATCH + (b0 + q)) * BLKS + blk] = s;
    }

    // ---- per-group finalize: last of this group's 49 blocks ----
    __shared__ int lastFlag;
    __threadfence();
    __syncthreads();
    if (tid == 0) lastFlag = (atomicAdd(&g_ctrs[grp], 1u) == BLKX - 1);
    __syncthreads();
    if (!lastFlag) return;

    __threadfence();   // acquire: this group's partials visible
    __shared__ float s_lg[GB][NC];
    if (tid < GB * NC) {            // 20 threads, one (b,c) pair each
        const int q = tid / NC, c = tid - q * NC;
        const float* base = g_part + (c * BATCH + (b0 + q)) * BLKS;  // 49 contiguous
        float s = __ldg(bias + c);
        #pragma unroll
        for (int k = 0; k < 12; k++) {
            float4 v = ldcg4(base + 4 * k);
            s += (v.x + v.y) + (v.z + v.w);
        }
        s += ldcg(base + 48);
        s_lg[q][c] = s;
    }
    __syncthreads();
    if (tid < GB) {
        float lg[NC];
        #pragma unroll
        for (int c = 0; c < NC; c++) lg[c] = s_lg[tid][c];
        float mx = lg[0];
        #pragma unroll
        for (int c = 1; c < NC; c++) mx = fmaxf(mx, lg[c]);
        float se = 0.f;
        #pragma unroll
        for (int c = 0; c < NC; c++) se += expf(lg[c] - mx);
        const float lse = logf(se);
        #pragma unroll
        for (int c = 0; c < NC; c++) out[(b0 + tid) * NC + c] = lg[c] - mx - lse;
    }
    if (tid == 0) g_ctrs[grp] = 0;   // reset own counter for next graph replay
}

extern "C" void kernel_launch(void* const* d_in, const int* in_sizes, int n_in,
                              void* d_out, int out_size) {
    const float* x    = (const float*)d_in[0];
    const float* rl1  = (const float*)d_in[1];
    const float* rl2  = (const float*)d_in[2];
    const float* W    = (const float*)d_in[3];
    const float* bias = (const float*)d_in[4];
    float* out        = (float*)d_out;

    k_fused<<<dim3(BLKX, NBG), TPB>>>(x, rl1, rl2, W, bias, out);
}